// round 1
// baseline (speedup 1.0000x reference)
#include <cuda_runtime.h>
#include <cstdint>

#define NN 50000
#define EE 800000
#define DD 128
#define FFD 512

// ---------------- scratch (static device globals; no allocs allowed) -------------
__device__ __align__(16) float g_h  [NN * DD];   // h = x @ W
__device__ __align__(16) float g_acc[NN * DD];   // unnormalized aggregation
__device__ __align__(16) float g_v1 [NN * DD];   // LN1 output (residual for LN2)
__device__ __align__(16) float g_u  [NN * DD];   // v1 + ffn(v1) pre-LN2
__device__ __align__(16) float g_t  [NN * FFD];  // relu(v1@W1+b1)
__device__ float g_ex[EE];
__device__ float g_asrc[NN];
__device__ float g_adst[NN];
__device__ float g_denom[NN];
__device__ int   g_idx32;   // 1 if edge_index is int32, 0 if int64

// ---------------- small helpers ----------------
__device__ __forceinline__ void load_edge(const void* ei, int e, int E, int& s, int& d) {
    if (g_idx32) {
        const int* p = (const int*)ei;
        s = p[e]; d = p[E + e];
    } else {
        const long long* p = (const long long*)ei;
        s = (int)p[e]; d = (int)p[(size_t)E + e];
    }
}

__device__ __forceinline__ void red_add_v4(float* addr, float4 v) {
    asm volatile("red.global.add.v4.f32 [%0], {%1,%2,%3,%4};"
                 :: "l"(addr), "f"(v.x), "f"(v.y), "f"(v.z), "f"(v.w)
                 : "memory");
}

__device__ __forceinline__ float warp_sum(float v) {
    #pragma unroll
    for (int o = 16; o > 0; o >>= 1) v += __shfl_xor_sync(0xffffffffu, v, o);
    return v;
}

// ---------------- dtype detection ----------------
__global__ void k_reset() { g_idx32 = 0; }

__global__ void k_detect(const unsigned int* w, int E) {
    int any = 0;
    for (int i = blockIdx.x * blockDim.x + threadIdx.x; i < E; i += gridDim.x * blockDim.x)
        if (w[2 * i + 1] != 0u) any = 1;
    if (any) g_idx32 = 1;
}

// ---------------- fp32 tiled GEMM: C[M,Nn] = A[M,K] @ B[K,Nn] (+bias,relu,resid) ----
// BM=64, BN=128, BK=32, 256 threads, 4x8 micro-tile per thread.
__global__ void k_gemm(const float* __restrict__ A, const float* __restrict__ B,
                       const float* __restrict__ bias, const float* __restrict__ resid,
                       float* __restrict__ C, int M, int K, int Nn, int do_relu) {
    __shared__ float As[32][64 + 4];
    __shared__ float Bs[32][128];

    const int tid = threadIdx.x;
    const int tx = tid & 15;       // 0..15 -> 8 cols each
    const int ty = tid >> 4;       // 0..15 -> 4 rows each
    const int row0 = blockIdx.x * 64;
    const int col0 = blockIdx.y * 128;

    float acc[4][8];
    #pragma unroll
    for (int i = 0; i < 4; i++)
        #pragma unroll
        for (int j = 0; j < 8; j++) acc[i][j] = 0.f;

    for (int kk = 0; kk < K; kk += 32) {
        // A tile 64x32 -> transposed into As[k][m]. 512 float4 loads, 2/thread.
        #pragma unroll
        for (int it = 0; it < 2; it++) {
            int idx = tid + it * 256;        // 0..511
            int r  = idx >> 3;               // row 0..63
            int c4 = idx & 7;                // float4 within k-chunk
            float4 v = make_float4(0.f, 0.f, 0.f, 0.f);
            int gr = row0 + r;
            if (gr < M) v = *(const float4*)(A + (size_t)gr * K + kk + c4 * 4);
            As[c4 * 4 + 0][r] = v.x;
            As[c4 * 4 + 1][r] = v.y;
            As[c4 * 4 + 2][r] = v.z;
            As[c4 * 4 + 3][r] = v.w;
        }
        // B tile 32x128. 1024 float4 loads, 4/thread.
        #pragma unroll
        for (int it = 0; it < 4; it++) {
            int idx = tid + it * 256;        // 0..1023
            int r  = idx >> 5;               // k 0..31
            int c4 = idx & 31;               // float4 col
            *(float4*)&Bs[r][c4 * 4] =
                *(const float4*)(B + (size_t)(kk + r) * Nn + col0 + c4 * 4);
        }
        __syncthreads();

        #pragma unroll
        for (int k = 0; k < 32; k++) {
            float4 a4 = *(const float4*)&As[k][ty * 4];
            float4 b0 = *(const float4*)&Bs[k][tx * 8];
            float4 b1 = *(const float4*)&Bs[k][tx * 8 + 4];
            float a[4] = {a4.x, a4.y, a4.z, a4.w};
            float b[8] = {b0.x, b0.y, b0.z, b0.w, b1.x, b1.y, b1.z, b1.w};
            #pragma unroll
            for (int i = 0; i < 4; i++)
                #pragma unroll
                for (int j = 0; j < 8; j++)
                    acc[i][j] = fmaf(a[i], b[j], acc[i][j]);
        }
        __syncthreads();
    }

    #pragma unroll
    for (int i = 0; i < 4; i++) {
        int gr = row0 + ty * 4 + i;
        if (gr >= M) continue;
        #pragma unroll
        for (int h4 = 0; h4 < 2; h4++) {
            int gc = col0 + tx * 8 + h4 * 4;
            float4 v = make_float4(acc[i][h4 * 4 + 0], acc[i][h4 * 4 + 1],
                                   acc[i][h4 * 4 + 2], acc[i][h4 * 4 + 3]);
            if (bias) {
                float4 bb = *(const float4*)(bias + gc);
                v.x += bb.x; v.y += bb.y; v.z += bb.z; v.w += bb.w;
            }
            if (do_relu) {
                v.x = fmaxf(v.x, 0.f); v.y = fmaxf(v.y, 0.f);
                v.z = fmaxf(v.z, 0.f); v.w = fmaxf(v.w, 0.f);
            }
            if (resid) {
                float4 rr = *(const float4*)(resid + (size_t)gr * Nn + gc);
                v.x += rr.x; v.y += rr.y; v.z += rr.z; v.w += rr.w;
            }
            *(float4*)(C + (size_t)gr * Nn + gc) = v;
        }
    }
}

// ---------------- per-node init: attention coefs + self-loop ----------------
// warp per node: a_src[i], a_dst[i], denom[i]=exp(lrelu(a_src+a_dst)), acc=h*e_loop
__global__ void k_node(const float* __restrict__ att_s, const float* __restrict__ att_d, int n) {
    int w = (blockIdx.x * blockDim.x + threadIdx.x) >> 5;
    int lane = threadIdx.x & 31;
    if (w >= n) return;
    float4 hv = ((const float4*)(g_h + (size_t)w * DD))[lane];
    float4 as = ((const float4*)att_s)[lane];
    float4 ad = ((const float4*)att_d)[lane];
    float s1 = hv.x * as.x + hv.y * as.y + hv.z * as.z + hv.w * as.w;
    float s2 = hv.x * ad.x + hv.y * ad.y + hv.z * ad.z + hv.w * ad.w;
    s1 = warp_sum(s1);
    s2 = warp_sum(s2);
    float al = s1 + s2;
    al = al > 0.f ? al : 0.2f * al;
    float el = expf(al);
    if (lane == 0) {
        g_asrc[w] = s1;
        g_adst[w] = s2;
        g_denom[w] = el;
    }
    float4 o = make_float4(hv.x * el, hv.y * el, hv.z * el, hv.w * el);
    ((float4*)(g_acc + (size_t)w * DD))[lane] = o;
}

// ---------------- edge pass 1: ex = exp(lrelu(asrc[s]+adst[d])), denom[d] += ex ---
__global__ void k_edge_alpha(const void* __restrict__ ei, int E) {
    int e = blockIdx.x * blockDim.x + threadIdx.x;
    if (e >= E) return;
    int s, d;
    load_edge(ei, e, E, s, d);
    float al = g_asrc[s] + g_adst[d];
    al = al > 0.f ? al : 0.2f * al;
    float ex = expf(al);
    g_ex[e] = ex;
    atomicAdd(&g_denom[d], ex);
}

// ---------------- edge pass 2: acc[d] += h[s] * ex[e]  (warp per edge) ----------
__global__ void k_edge_agg(const void* __restrict__ ei, int E) {
    int e = blockIdx.x * (blockDim.x >> 5) + (threadIdx.x >> 5);
    int lane = threadIdx.x & 31;
    if (e >= E) return;
    int s, d;
    load_edge(ei, e, E, s, d);
    float wgt = g_ex[e];
    float4 hv = ((const float4*)(g_h + (size_t)s * DD))[lane];
    float4 v = make_float4(hv.x * wgt, hv.y * wgt, hv.z * wgt, hv.w * wgt);
    red_add_v4(g_acc + (size_t)d * DD + lane * 4, v);
}

// ---------------- fused normalize + bias + residual + LayerNorm1 -> v1 ----------
__global__ void k_ln1(const float* __restrict__ x, const float* __restrict__ gbias,
                      const float* __restrict__ gam, const float* __restrict__ bet, int n) {
    int w = (blockIdx.x * blockDim.x + threadIdx.x) >> 5;
    int lane = threadIdx.x & 31;
    if (w >= n) return;
    float inv = 1.f / (g_denom[w] + 1e-16f);
    float4 a = ((const float4*)(g_acc + (size_t)w * DD))[lane];
    float4 gb = ((const float4*)gbias)[lane];
    float4 xv = ((const float4*)(x + (size_t)w * DD))[lane];
    float4 p = make_float4(a.x * inv + gb.x + xv.x, a.y * inv + gb.y + xv.y,
                           a.z * inv + gb.z + xv.z, a.w * inv + gb.w + xv.w);
    float s1 = p.x + p.y + p.z + p.w;
    float s2 = p.x * p.x + p.y * p.y + p.z * p.z + p.w * p.w;
    s1 = warp_sum(s1);
    s2 = warp_sum(s2);
    float mean = s1 * (1.f / DD);
    float var = s2 * (1.f / DD) - mean * mean;
    float rs = rsqrtf(var + 1e-5f);
    float4 gm = ((const float4*)gam)[lane];
    float4 bt = ((const float4*)bet)[lane];
    float4 o = make_float4((p.x - mean) * rs * gm.x + bt.x,
                           (p.y - mean) * rs * gm.y + bt.y,
                           (p.z - mean) * rs * gm.z + bt.z,
                           (p.w - mean) * rs * gm.w + bt.w);
    ((float4*)(g_v1 + (size_t)w * DD))[lane] = o;
}

// ---------------- LayerNorm2: d_out = LN(g_u) -----------------------------------
__global__ void k_ln2(const float* __restrict__ gam, const float* __restrict__ bet,
                      float* __restrict__ out, int n) {
    int w = (blockIdx.x * blockDim.x + threadIdx.x) >> 5;
    int lane = threadIdx.x & 31;
    if (w >= n) return;
    float4 p = ((const float4*)(g_u + (size_t)w * DD))[lane];
    float s1 = p.x + p.y + p.z + p.w;
    float s2 = p.x * p.x + p.y * p.y + p.z * p.z + p.w * p.w;
    s1 = warp_sum(s1);
    s2 = warp_sum(s2);
    float mean = s1 * (1.f / DD);
    float var = s2 * (1.f / DD) - mean * mean;
    float rs = rsqrtf(var + 1e-5f);
    float4 gm = ((const float4*)gam)[lane];
    float4 bt = ((const float4*)bet)[lane];
    float4 o = make_float4((p.x - mean) * rs * gm.x + bt.x,
                           (p.y - mean) * rs * gm.y + bt.y,
                           (p.z - mean) * rs * gm.z + bt.z,
                           (p.w - mean) * rs * gm.w + bt.w);
    ((float4*)(out + (size_t)w * DD))[lane] = o;
}

// ---------------- launch ----------------
extern "C" void kernel_launch(void* const* d_in, const int* in_sizes, int n_in,
                              void* d_out, int out_size) {
    const float* x        = (const float*)d_in[0];
    const void*  ei       = d_in[1];
    // d_in[2] = edge_attr (ignored; GATConv built with edge_dim=None)
    const float* W        = (const float*)d_in[3];
    const float* att_src  = (const float*)d_in[4];
    const float* att_dst  = (const float*)d_in[5];
    const float* gat_bias = (const float*)d_in[6];
    const float* W1       = (const float*)d_in[7];
    const float* b1       = (const float*)d_in[8];
    const float* W2       = (const float*)d_in[9];
    const float* b2       = (const float*)d_in[10];
    const float* ln1_g    = (const float*)d_in[11];
    const float* ln1_b    = (const float*)d_in[12];
    const float* ln2_g    = (const float*)d_in[13];
    const float* ln2_b    = (const float*)d_in[14];
    float* out = (float*)d_out;

    const int n = in_sizes[0] / DD;
    const int E = in_sizes[1] / 2;

    float *ph, *pv1, *pu, *pt;
    cudaGetSymbolAddress((void**)&ph,  g_h);
    cudaGetSymbolAddress((void**)&pv1, g_v1);
    cudaGetSymbolAddress((void**)&pu,  g_u);
    cudaGetSymbolAddress((void**)&pt,  g_t);

    // 0. edge_index dtype detection (int32 vs int64)
    k_reset<<<1, 1>>>();
    k_detect<<<512, 256>>>((const unsigned int*)ei, E);

    // 1. h = x @ W
    {
        dim3 grid((n + 63) / 64, DD / 128);
        k_gemm<<<grid, 256>>>(x, W, nullptr, nullptr, ph, n, DD, DD, 0);
    }

    // 2. per-node attention coefs + self-loop init
    k_node<<<(n * 32 + 255) / 256, 256>>>(att_src, att_dst, n);

    // 3. edge alphas + denom accumulation
    k_edge_alpha<<<(E + 255) / 256, 256>>>(ei, E);

    // 4. edge aggregation (warp per edge, vector red)
    k_edge_agg<<<(E + 7) / 8, 256>>>(ei, E);

    // 5. normalize + gat_bias + residual + LN1 -> v1
    k_ln1<<<(n * 32 + 255) / 256, 256>>>(x, gat_bias, ln1_g, ln1_b, n);

    // 6. t = relu(v1 @ W1 + b1)
    {
        dim3 grid((n + 63) / 64, FFD / 128);
        k_gemm<<<grid, 256>>>(pv1, W1, b1, nullptr, pt, n, DD, FFD, 1);
    }

    // 7. u = t @ W2 + b2 + v1
    {
        dim3 grid((n + 63) / 64, DD / 128);
        k_gemm<<<grid, 256>>>(pt, W2, b2, pv1, pu, n, FFD, DD, 0);
    }

    // 8. d_out = LN2(u)
    k_ln2<<<(n * 32 + 255) / 256, 256>>>(ln2_g, ln2_b, out, n);
}

// round 3
// speedup vs baseline: 1.6011x; 1.6011x over previous
#include <cuda_runtime.h>
#include <cuda_bf16.h>
#include <mma.h>
#include <cstdint>

using namespace nvcuda;

#define NN 50000
#define EE 800000
#define DD 128
#define FFD 512

// ---------------- scratch (static device globals; no allocs allowed) -------------
__device__ __align__(16) float g_h  [NN * DD];   // h = x @ W (fp32, edge agg needs it)
__device__ __align__(16) float g_acc[NN * DD];   // unnormalized aggregation
__device__ __align__(16) float g_v1 [NN * DD];   // LN1 output (residual for LN2)
__device__ __align__(16) float g_u  [NN * DD];   // v1 + ffn(v1) pre-LN2
__device__ float g_ex[EE];
__device__ float g_asrc[NN];
__device__ float g_adst[NN];
__device__ float g_denom[NN];
__device__ int   g_idx32;   // 1 if edge_index is int32, 0 if int64

// bf16 split operands for tensor-core GEMMs
__device__ __align__(16) __nv_bfloat16 g_xh [NN * DD];
__device__ __align__(16) __nv_bfloat16 g_xl [NN * DD];
__device__ __align__(16) __nv_bfloat16 g_v1h[NN * DD];
__device__ __align__(16) __nv_bfloat16 g_v1l[NN * DD];
__device__ __align__(16) __nv_bfloat16 g_th [NN * FFD];
__device__ __align__(16) __nv_bfloat16 g_tl [NN * FFD];
// weights, transposed to [N,K] K-major, split
__device__ __align__(16) __nv_bfloat16 g_wt0h[DD * DD];
__device__ __align__(16) __nv_bfloat16 g_wt0l[DD * DD];
__device__ __align__(16) __nv_bfloat16 g_wt1h[FFD * DD];
__device__ __align__(16) __nv_bfloat16 g_wt1l[FFD * DD];
__device__ __align__(16) __nv_bfloat16 g_wt2h[DD * FFD];
__device__ __align__(16) __nv_bfloat16 g_wt2l[DD * FFD];

// ---------------- small helpers ----------------
__device__ __forceinline__ void load_edge(const void* ei, int e, int E, int& s, int& d) {
    if (g_idx32) {
        const int* p = (const int*)ei;
        s = p[e]; d = p[E + e];
    } else {
        const long long* p = (const long long*)ei;
        s = (int)p[e]; d = (int)p[(size_t)E + e];
    }
}

__device__ __forceinline__ void red_add_v4(float* addr, float4 v) {
    asm volatile("red.global.add.v4.f32 [%0], {%1,%2,%3,%4};"
                 :: "l"(addr), "f"(v.x), "f"(v.y), "f"(v.z), "f"(v.w) : "memory");
}

__device__ __forceinline__ float warp_sum(float v) {
    #pragma unroll
    for (int o = 16; o > 0; o >>= 1) v += __shfl_xor_sync(0xffffffffu, v, o);
    return v;
}

__device__ __forceinline__ void split1(float v, __nv_bfloat16& h, __nv_bfloat16& l) {
    h = __float2bfloat16(v);
    l = __float2bfloat16(v - __bfloat162float(h));
}

// ---------------- dtype detection ----------------
__global__ void k_reset() { g_idx32 = 0; }

__global__ void k_detect(const unsigned int* w, int E) {
    int any = 0;
    for (int i = blockIdx.x * blockDim.x + threadIdx.x; i < E; i += gridDim.x * blockDim.x)
        if (w[2 * i + 1] != 0u) any = 1;
    if (any) g_idx32 = 1;
}

// ---------------- bf16 split conversion (row-major, vectorized) -----------------
__global__ void k_split4(const float* __restrict__ in, __nv_bfloat16* __restrict__ hi,
                         __nv_bfloat16* __restrict__ lo, int n4) {
    int i = blockIdx.x * blockDim.x + threadIdx.x;
    if (i >= n4) return;
    float4 v = ((const float4*)in)[i];
    __nv_bfloat16 h0, h1, h2, h3, l0, l1, l2, l3;
    split1(v.x, h0, l0); split1(v.y, h1, l1); split1(v.z, h2, l2); split1(v.w, h3, l3);
    ((__nv_bfloat162*)hi)[2 * i]     = __nv_bfloat162(h0, h1);
    ((__nv_bfloat162*)hi)[2 * i + 1] = __nv_bfloat162(h2, h3);
    ((__nv_bfloat162*)lo)[2 * i]     = __nv_bfloat162(l0, l1);
    ((__nv_bfloat162*)lo)[2 * i + 1] = __nv_bfloat162(l2, l3);
}

// ---------------- weight transpose + split: W[K,Nn] -> Wt[N,K] hi/lo ------------
__global__ void k_tsplit(const float* __restrict__ W, __nv_bfloat16* __restrict__ hi,
                         __nv_bfloat16* __restrict__ lo, int K, int Nn) {
    int idx = blockIdx.x * blockDim.x + threadIdx.x;
    if (idx >= K * Nn) return;
    int k = idx / Nn, n = idx % Nn;
    __nv_bfloat16 h, l;
    split1(W[idx], h, l);
    hi[(size_t)n * K + k] = h;
    lo[(size_t)n * K + k] = l;
}

// ---------------- wmma (HMMA) bf16-split GEMM ----------------------------------
// C[M,Nn] = A[M,K] @ Bt[Nn,K]^T with 3-term hi/lo compensation.
// CTA tile 128x128, 256 threads (8 warps as 2x4), warp tile 64x32.
// mode 0: Cf = r                     (h)
// mode 1: Ch/Cl = split(relu(r+b))   (t)
// mode 2: Cf = r + b + resid         (u)
#define SLDA 48                         // smem ld for bf16 tiles (96B rows, 16B-aligned)
#define CLD  132                        // smem ld for fp32 C stage
#define WG_SMEM (128 * CLD * 4)         // 67584 >= 4*128*48*2 = 49152

__global__ void __launch_bounds__(256)
k_wgemm(const __nv_bfloat16* __restrict__ Ah, const __nv_bfloat16* __restrict__ Al,
        const __nv_bfloat16* __restrict__ Bh, const __nv_bfloat16* __restrict__ Bl,
        float* __restrict__ Cf, __nv_bfloat16* __restrict__ Ch, __nv_bfloat16* __restrict__ Cl,
        const float* __restrict__ bias, const float* __restrict__ resid,
        int M, int K, int Nn, int mode) {
    extern __shared__ char smem[];
    __nv_bfloat16* sAh = (__nv_bfloat16*)smem;           // [128][SLDA]
    __nv_bfloat16* sAl = sAh + 128 * SLDA;
    __nv_bfloat16* sBh = sAl + 128 * SLDA;
    __nv_bfloat16* sBl = sBh + 128 * SLDA;
    float* sC = (float*)smem;                            // [128][CLD] (reused)

    const int tid = threadIdx.x;
    const int wid = tid >> 5;
    const int warp_m = wid & 1;          // 0..1  (64 rows each)
    const int warp_n = wid >> 1;         // 0..3  (32 cols each)
    const int row0 = blockIdx.x * 128;
    const int col0 = blockIdx.y * 128;

    wmma::fragment<wmma::accumulator, 16, 16, 16, float> acc[4][2];
    #pragma unroll
    for (int i = 0; i < 4; i++)
        #pragma unroll
        for (int j = 0; j < 2; j++) wmma::fill_fragment(acc[i][j], 0.f);

    for (int kk = 0; kk < K; kk += 32) {
        // stage 128x32 bf16 tiles for A hi/lo and B hi/lo
        #pragma unroll
        for (int it = 0; it < 2; it++) {
            int i = tid + it * 256;      // 0..511
            int r = i >> 2, q = i & 3;   // row, uint4(8 bf16) within 32-col chunk
            size_t aoff = (size_t)(row0 + r) * K + kk + q * 8;
            size_t boff = (size_t)(col0 + r) * K + kk + q * 8;
            uint4 vah = make_uint4(0, 0, 0, 0), val = make_uint4(0, 0, 0, 0);
            if (row0 + r < M) {
                vah = *(const uint4*)(Ah + aoff);
                val = *(const uint4*)(Al + aoff);
            }
            *(uint4*)(sAh + r * SLDA + q * 8) = vah;
            *(uint4*)(sAl + r * SLDA + q * 8) = val;
            *(uint4*)(sBh + r * SLDA + q * 8) = *(const uint4*)(Bh + boff);
            *(uint4*)(sBl + r * SLDA + q * 8) = *(const uint4*)(Bl + boff);
        }
        __syncthreads();

        #pragma unroll
        for (int ks = 0; ks < 32; ks += 16) {
            wmma::fragment<wmma::matrix_a, 16, 16, 16, __nv_bfloat16, wmma::row_major> ah[4], al[4];
            wmma::fragment<wmma::matrix_b, 16, 16, 16, __nv_bfloat16, wmma::col_major> bh[2], bl[2];
            #pragma unroll
            for (int i = 0; i < 4; i++) {
                const __nv_bfloat16* pa = sAh + (warp_m * 64 + i * 16) * SLDA + ks;
                wmma::load_matrix_sync(ah[i], pa, SLDA);
                wmma::load_matrix_sync(al[i], pa + 128 * SLDA, SLDA);   // sAl
            }
            #pragma unroll
            for (int j = 0; j < 2; j++) {
                const __nv_bfloat16* pb = sBh + (warp_n * 32 + j * 16) * SLDA + ks;
                wmma::load_matrix_sync(bh[j], pb, SLDA);
                wmma::load_matrix_sync(bl[j], pb + 128 * SLDA, SLDA);   // sBl
            }
            #pragma unroll
            for (int i = 0; i < 4; i++)
                #pragma unroll
                for (int j = 0; j < 2; j++) {
                    wmma::mma_sync(acc[i][j], ah[i], bh[j], acc[i][j]);
                    wmma::mma_sync(acc[i][j], ah[i], bl[j], acc[i][j]);
                    wmma::mma_sync(acc[i][j], al[i], bh[j], acc[i][j]);
                }
        }
        __syncthreads();
    }

    // epilogue: stage C in smem, then fused coalesced stores
    #pragma unroll
    for (int i = 0; i < 4; i++)
        #pragma unroll
        for (int j = 0; j < 2; j++)
            wmma::store_matrix_sync(sC + (warp_m * 64 + i * 16) * CLD + warp_n * 32 + j * 16,
                                    acc[i][j], CLD, wmma::mem_row_major);
    __syncthreads();

    #pragma unroll
    for (int it = 0; it < 16; it++) {
        int i = tid + it * 256;          // 0..4095
        int rr = i >> 5, q = i & 31;     // row, float4 col group
        int gr = row0 + rr;
        if (gr >= M) continue;
        int gc = col0 + q * 4;
        float4 v = *(const float4*)(sC + rr * CLD + q * 4);
        if (mode != 0) {
            const float4 bb = *(const float4*)(bias + gc);
            v.x += bb.x; v.y += bb.y; v.z += bb.z; v.w += bb.w;
        }
        if (mode == 1) {
            v.x = fmaxf(v.x, 0.f); v.y = fmaxf(v.y, 0.f);
            v.z = fmaxf(v.z, 0.f); v.w = fmaxf(v.w, 0.f);
            __nv_bfloat16 h0, h1, h2, h3, l0, l1, l2, l3;
            split1(v.x, h0, l0); split1(v.y, h1, l1);
            split1(v.z, h2, l2); split1(v.w, h3, l3);
            size_t ob = (size_t)gr * Nn + gc;
            *(__nv_bfloat162*)(Ch + ob)     = __nv_bfloat162(h0, h1);
            *(__nv_bfloat162*)(Ch + ob + 2) = __nv_bfloat162(h2, h3);
            *(__nv_bfloat162*)(Cl + ob)     = __nv_bfloat162(l0, l1);
            *(__nv_bfloat162*)(Cl + ob + 2) = __nv_bfloat162(l2, l3);
        } else {
            if (mode == 2) {
                const float4 rr4 = *(const float4*)(resid + (size_t)gr * Nn + gc);
                v.x += rr4.x; v.y += rr4.y; v.z += rr4.z; v.w += rr4.w;
            }
            *(float4*)(Cf + (size_t)gr * Nn + gc) = v;
        }
    }
}

// ---------------- per-node init: attention coefs + self-loop ----------------
__global__ void k_node(const float* __restrict__ att_s, const float* __restrict__ att_d, int n) {
    int w = (blockIdx.x * blockDim.x + threadIdx.x) >> 5;
    int lane = threadIdx.x & 31;
    if (w >= n) return;
    float4 hv = ((const float4*)(g_h + (size_t)w * DD))[lane];
    float4 as = ((const float4*)att_s)[lane];
    float4 ad = ((const float4*)att_d)[lane];
    float s1 = hv.x * as.x + hv.y * as.y + hv.z * as.z + hv.w * as.w;
    float s2 = hv.x * ad.x + hv.y * ad.y + hv.z * ad.z + hv.w * ad.w;
    s1 = warp_sum(s1);
    s2 = warp_sum(s2);
    float al = s1 + s2;
    al = al > 0.f ? al : 0.2f * al;
    float el = expf(al);
    if (lane == 0) {
        g_asrc[w] = s1;
        g_adst[w] = s2;
        g_denom[w] = el;
    }
    float4 o = make_float4(hv.x * el, hv.y * el, hv.z * el, hv.w * el);
    ((float4*)(g_acc + (size_t)w * DD))[lane] = o;
}

// ---------------- edge pass 1: ex + denom accumulation ----------------
__global__ void k_edge_alpha(const void* __restrict__ ei, int E) {
    int e = blockIdx.x * blockDim.x + threadIdx.x;
    if (e >= E) return;
    int s, d;
    load_edge(ei, e, E, s, d);
    float al = g_asrc[s] + g_adst[d];
    al = al > 0.f ? al : 0.2f * al;
    float ex = expf(al);
    g_ex[e] = ex;
    atomicAdd(&g_denom[d], ex);
}

// ---------------- edge pass 2: acc[d] += h[s] * ex[e]  (warp per edge) ----------
__global__ void k_edge_agg(const void* __restrict__ ei, int E) {
    int e = blockIdx.x * (blockDim.x >> 5) + (threadIdx.x >> 5);
    int lane = threadIdx.x & 31;
    if (e >= E) return;
    int s, d;
    load_edge(ei, e, E, s, d);
    float wgt = g_ex[e];
    float4 hv = ((const float4*)(g_h + (size_t)s * DD))[lane];
    float4 v = make_float4(hv.x * wgt, hv.y * wgt, hv.z * wgt, hv.w * wgt);
    red_add_v4(g_acc + (size_t)d * DD + lane * 4, v);
}

// ---------------- fused normalize + bias + residual + LN1 -> v1 (+hi/lo) -------
__global__ void k_ln1(const float* __restrict__ x, const float* __restrict__ gbias,
                      const float* __restrict__ gam, const float* __restrict__ bet, int n) {
    int w = (blockIdx.x * blockDim.x + threadIdx.x) >> 5;
    int lane = threadIdx.x & 31;
    if (w >= n) return;
    float inv = 1.f / (g_denom[w] + 1e-16f);
    float4 a = ((const float4*)(g_acc + (size_t)w * DD))[lane];
    float4 gb = ((const float4*)gbias)[lane];
    float4 xv = ((const float4*)(x + (size_t)w * DD))[lane];
    float4 p = make_float4(a.x * inv + gb.x + xv.x, a.y * inv + gb.y + xv.y,
                           a.z * inv + gb.z + xv.z, a.w * inv + gb.w + xv.w);
    float s1 = p.x + p.y + p.z + p.w;
    float s2 = p.x * p.x + p.y * p.y + p.z * p.z + p.w * p.w;
    s1 = warp_sum(s1);
    s2 = warp_sum(s2);
    float mean = s1 * (1.f / DD);
    float var = s2 * (1.f / DD) - mean * mean;
    float rs = rsqrtf(var + 1e-5f);
    float4 gm = ((const float4*)gam)[lane];
    float4 bt = ((const float4*)bet)[lane];
    float4 o = make_float4((p.x - mean) * rs * gm.x + bt.x,
                           (p.y - mean) * rs * gm.y + bt.y,
                           (p.z - mean) * rs * gm.z + bt.z,
                           (p.w - mean) * rs * gm.w + bt.w);
    ((float4*)(g_v1 + (size_t)w * DD))[lane] = o;
    __nv_bfloat16 h0, h1, h2, h3, l0, l1, l2, l3;
    split1(o.x, h0, l0); split1(o.y, h1, l1); split1(o.z, h2, l2); split1(o.w, h3, l3);
    size_t ob = (size_t)w * DD + lane * 4;
    *(__nv_bfloat162*)(g_v1h + ob)     = __nv_bfloat162(h0, h1);
    *(__nv_bfloat162*)(g_v1h + ob + 2) = __nv_bfloat162(h2, h3);
    *(__nv_bfloat162*)(g_v1l + ob)     = __nv_bfloat162(l0, l1);
    *(__nv_bfloat162*)(g_v1l + ob + 2) = __nv_bfloat162(l2, l3);
}

// ---------------- LayerNorm2: d_out = LN(g_u) -----------------------------------
__global__ void k_ln2(const float* __restrict__ gam, const float* __restrict__ bet,
                      float* __restrict__ out, int n) {
    int w = (blockIdx.x * blockDim.x + threadIdx.x) >> 5;
    int lane = threadIdx.x & 31;
    if (w >= n) return;
    float4 p = ((const float4*)(g_u + (size_t)w * DD))[lane];
    float s1 = p.x + p.y + p.z + p.w;
    float s2 = p.x * p.x + p.y * p.y + p.z * p.z + p.w * p.w;
    s1 = warp_sum(s1);
    s2 = warp_sum(s2);
    float mean = s1 * (1.f / DD);
    float var = s2 * (1.f / DD) - mean * mean;
    float rs = rsqrtf(var + 1e-5f);
    float4 gm = ((const float4*)gam)[lane];
    float4 bt = ((const float4*)bet)[lane];
    float4 o = make_float4((p.x - mean) * rs * gm.x + bt.x,
                           (p.y - mean) * rs * gm.y + bt.y,
                           (p.z - mean) * rs * gm.z + bt.z,
                           (p.w - mean) * rs * gm.w + bt.w);
    ((float4*)(out + (size_t)w * DD))[lane] = o;
}

// ---------------- launch ----------------
extern "C" void kernel_launch(void* const* d_in, const int* in_sizes, int n_in,
                              void* d_out, int out_size) {
    const float* x        = (const float*)d_in[0];
    const void*  ei       = d_in[1];
    // d_in[2] = edge_attr (ignored; GATConv built with edge_dim=None)
    const float* W        = (const float*)d_in[3];
    const float* att_src  = (const float*)d_in[4];
    const float* att_dst  = (const float*)d_in[5];
    const float* gat_bias = (const float*)d_in[6];
    const float* W1       = (const float*)d_in[7];
    const float* b1       = (const float*)d_in[8];
    const float* W2       = (const float*)d_in[9];
    const float* b2       = (const float*)d_in[10];
    const float* ln1_g    = (const float*)d_in[11];
    const float* ln1_b    = (const float*)d_in[12];
    const float* ln2_g    = (const float*)d_in[13];
    const float* ln2_b    = (const float*)d_in[14];
    float* out = (float*)d_out;

    const int n = in_sizes[0] / DD;
    const int E = in_sizes[1] / 2;
    const int mtiles = (n + 127) / 128;

    float *ph, *pv1, *pu;
    __nv_bfloat16 *pxh, *pxl, *pv1h, *pv1l, *pth, *ptl;
    __nv_bfloat16 *pw0h, *pw0l, *pw1h, *pw1l, *pw2h, *pw2l;
    cudaGetSymbolAddress((void**)&ph,   g_h);
    cudaGetSymbolAddress((void**)&pv1,  g_v1);
    cudaGetSymbolAddress((void**)&pu,   g_u);
    cudaGetSymbolAddress((void**)&pxh,  g_xh);
    cudaGetSymbolAddress((void**)&pxl,  g_xl);
    cudaGetSymbolAddress((void**)&pv1h, g_v1h);
    cudaGetSymbolAddress((void**)&pv1l, g_v1l);
    cudaGetSymbolAddress((void**)&pth,  g_th);
    cudaGetSymbolAddress((void**)&ptl,  g_tl);
    cudaGetSymbolAddress((void**)&pw0h, g_wt0h);
    cudaGetSymbolAddress((void**)&pw0l, g_wt0l);
    cudaGetSymbolAddress((void**)&pw1h, g_wt1h);
    cudaGetSymbolAddress((void**)&pw1l, g_wt1l);
    cudaGetSymbolAddress((void**)&pw2h, g_wt2h);
    cudaGetSymbolAddress((void**)&pw2l, g_wt2l);

    cudaFuncSetAttribute(k_wgemm, cudaFuncAttributeMaxDynamicSharedMemorySize, WG_SMEM);

    // 0. edge_index dtype detection (int32 vs int64)
    k_reset<<<1, 1>>>();
    k_detect<<<512, 256>>>((const unsigned int*)ei, E);

    // operand prep: split x; transpose+split weights
    k_split4<<<(n * DD / 4 + 255) / 256, 256>>>(x, pxh, pxl, n * DD / 4);
    k_tsplit<<<(DD * DD + 255) / 256, 256>>>(W, pw0h, pw0l, DD, DD);
    k_tsplit<<<(DD * FFD + 255) / 256, 256>>>(W1, pw1h, pw1l, DD, FFD);
    k_tsplit<<<(FFD * DD + 255) / 256, 256>>>(W2, pw2h, pw2l, FFD, DD);

    // 1. h = x @ W  (HMMA)
    {
        dim3 grid(mtiles, 1);
        k_wgemm<<<grid, 256, WG_SMEM>>>(pxh, pxl, pw0h, pw0l, ph, nullptr, nullptr,
                                        nullptr, nullptr, n, DD, DD, 0);
    }

    // 2. per-node attention coefs + self-loop init
    k_node<<<(n * 32 + 255) / 256, 256>>>(att_src, att_dst, n);

    // 3. edge alphas + denom accumulation
    k_edge_alpha<<<(E + 255) / 256, 256>>>(ei, E);

    // 4. edge aggregation (warp per edge, vector red)
    k_edge_agg<<<(E + 7) / 8, 256>>>(ei, E);

    // 5. normalize + gat_bias + residual + LN1 -> v1 (+ bf16 split)
    k_ln1<<<(n * 32 + 255) / 256, 256>>>(x, gat_bias, ln1_g, ln1_b, n);

    // 6. t = relu(v1 @ W1 + b1)  (HMMA, bf16-split output)
    {
        dim3 grid(mtiles, FFD / 128);
        k_wgemm<<<grid, 256, WG_SMEM>>>(pv1h, pv1l, pw1h, pw1l, nullptr, pth, ptl,
                                        b1, nullptr, n, DD, FFD, 1);
    }

    // 7. u = t @ W2 + b2 + v1  (HMMA)
    {
        dim3 grid(mtiles, 1);
        k_wgemm<<<grid, 256, WG_SMEM>>>(pth, ptl, pw2h, pw2l, pu, nullptr, nullptr,
                                        b2, pv1, n, FFD, DD, 2);
    }

    // 8. d_out = LN2(u)
    k_ln2<<<(n * 32 + 255) / 256, 256>>>(ln2_g, ln2_b, out, n);
}